// round 16
// baseline (speedup 1.0000x reference)
#include <cuda_runtime.h>
#include <cuda_fp16.h>

#define N_NODES 50000
#define N_EDGES 800000
#define PREP_BLOCKS 592
#define PREP_TPB 512

#define H2(u) (*(__half2*)&(u))

// ---------------- device scratch (static: no allocation allowed) ----------------
__device__ int g_is64;
__device__ __align__(16) int g_deg[N_NODES];
__device__ __align__(16) int g_offs[N_NODES + 4];
__device__ __align__(16) int g_cursor[N_NODES];
__device__ __align__(16) int g_esrc[N_EDGES];
__device__ int g_bsum[128];
__device__ __align__(16) __half g_feat16[(size_t)N_NODES * 128];
__device__ __align__(16) __half g_agg16[(size_t)N_NODES * 128];
__device__ __align__(16) __half g_p2h[(size_t)N_NODES * 64];
__device__ __align__(16) __half g_w1t[128 * 256];   // [n][k] fp16
__device__ __align__(16) __half g_w2t[128 * 128];   // [n][k] fp16

// ---------------- grid barrier (592 x 512-thread blocks: 4/SM, all co-resident) ----------------
__device__ unsigned g_bar_count = 0;
__device__ volatile unsigned g_bar_gen = 0;

__device__ __forceinline__ void grid_barrier() {
    __syncthreads();
    if (threadIdx.x == 0) {
        unsigned gen = g_bar_gen;
        __threadfence();
        if (atomicAdd(&g_bar_count, 1u) == gridDim.x - 1) {
            g_bar_count = 0;
            __threadfence();
            g_bar_gen = gen + 1;
        } else {
            while (g_bar_gen == gen) { }
        }
        __threadfence();
    }
    __syncthreads();
}

__device__ __forceinline__ int wscan_incl(int x, int lane) {
    #pragma unroll
    for (int o = 1; o < 32; o <<= 1) {
        int y = __shfl_up_sync(0xFFFFFFFFu, x, o);
        if (lane >= o) x += y;
    }
    return x;
}

// ---------------- mega prep kernel ----------------
__global__ __launch_bounds__(PREP_TPB, 4) void k_prep(
    const float4* __restrict__ feat, const void* __restrict__ src, const void* __restrict__ dst,
    const float* __restrict__ Ws1, const float* __restrict__ Wn1,
    const float* __restrict__ Ws2, const float* __restrict__ Wn2,
    int M, int E)
{
    int tid = threadIdx.x, b = blockIdx.x;
    int lane = tid & 31, wid = tid >> 5;    // wid 0..15
    int gt = b * PREP_TPB + tid;
    int GT = gridDim.x * PREP_TPB;
    __shared__ int s_any;
    __shared__ int wsum[16];

    // ---- Phase A: detect dtype + zero degree ----
    if (b == 0) {
        if (tid == 0) s_any = 0;
        __syncthreads();
        if (((const unsigned*)src)[2 * tid + 1]) s_any = 1;  // benign race
        __syncthreads();
        if (tid == 0) g_is64 = (s_any == 0) ? 1 : 0;
    }
    for (int i = gt; i < M; i += GT) g_deg[i] = 0;
    grid_barrier();

    // ---- Phase B: histogram + feat->fp16 + weight prep (independent, overlapped) ----
    int is64 = g_is64;
    for (int base = gt * 4; base < E; base += GT * 4) {
        if (base + 3 < E) {
            int d0, d1, d2, d3;
            if (is64) {
                int4 w0 = ((const int4*)dst)[base >> 1];
                int4 w1 = ((const int4*)dst)[(base >> 1) + 1];
                d0 = w0.x; d1 = w0.z; d2 = w1.x; d3 = w1.z;
            } else {
                int4 w = ((const int4*)dst)[base >> 2];
                d0 = w.x; d1 = w.y; d2 = w.z; d3 = w.w;
            }
            atomicAdd(&g_deg[d0], 1); atomicAdd(&g_deg[d1], 1);
            atomicAdd(&g_deg[d2], 1); atomicAdd(&g_deg[d3], 1);
        } else {
            for (int e = base; e < E; e++) {
                int d = is64 ? (int)((const long long*)dst)[e] : ((const int*)dst)[e];
                atomicAdd(&g_deg[d], 1);
            }
        }
    }
    int TU = (M * 128) / 8;
    for (int i = gt; i < TU; i += GT) {
        float4 a = feat[2 * i], c = feat[2 * i + 1];
        __half2 h0 = __floats2half2_rn(a.x, a.y);
        __half2 h1 = __floats2half2_rn(a.z, a.w);
        __half2 h2 = __floats2half2_rn(c.x, c.y);
        __half2 h3 = __floats2half2_rn(c.z, c.w);
        ((uint4*)g_feat16)[i] = make_uint4(*(unsigned*)&h0, *(unsigned*)&h1,
                                           *(unsigned*)&h2, *(unsigned*)&h3);
    }
    for (int i = gt; i < 128 * 256; i += GT) {
        int k = i >> 7, n = i & 127;
        float v = (k < 128) ? Ws1[k * 128 + n] : Wn1[(k - 128) * 128 + n];
        g_w1t[n * 256 + k] = __float2half_rn(v);
    }
    for (int i = gt; i < 128 * 128; i += GT) {
        int k = i >> 7, n = i & 127;
        float v = (n < 64) ? Ws2[k * 64 + n] : Wn2[k * 64 + (n - 64)];
        g_w2t[n * 128 + k] = __float2half_rn(v);
    }
    grid_barrier();

    // ---- Phase C1: per-block local scan (512 elems per block) ----
    int nsb = (M + PREP_TPB - 1) / PREP_TPB;     // 98
    int v = 0, excl = 0;
    if (b < nsb) {
        int i = b * PREP_TPB + tid;
        v = (i < M) ? g_deg[i] : 0;
        int x = wscan_incl(v, lane);
        if (lane == 31) wsum[wid] = x;
        __syncthreads();
        if (wid == 0) {
            int w = (lane < 16) ? wsum[lane] : 0;
            w = wscan_incl(w, lane);
            if (lane < 16) wsum[lane] = w;
        }
        __syncthreads();
        int wex = wid ? wsum[wid - 1] : 0;
        excl = wex + x - v;
        if (tid == 0) g_bsum[b] = wsum[15];
    }
    grid_barrier();

    // ---- Phase C2: apply (each block redundantly computes its own carry) ----
    if (b < nsb) {
        int carry = 0;
        for (int idx = lane; idx < b; idx += 32) carry += g_bsum[idx];
        #pragma unroll
        for (int o = 16; o > 0; o >>= 1) carry += __shfl_xor_sync(0xFFFFFFFFu, carry, o);
        int i = b * PREP_TPB + tid;
        int e2 = carry + excl;
        if (i < M) {
            g_offs[i] = e2;
            g_cursor[i] = e2;
            if (i == M - 1) g_offs[M] = e2 + v;
        }
    }
    grid_barrier();

    // ---- Phase D: scatter edges into CSC ----
    for (int base = gt * 4; base < E; base += GT * 4) {
        if (base + 3 < E) {
            int s0, s1, s2, s3, d0, d1, d2, d3;
            if (is64) {
                int4 a0 = ((const int4*)src)[base >> 1];
                int4 a1 = ((const int4*)src)[(base >> 1) + 1];
                int4 b0 = ((const int4*)dst)[base >> 1];
                int4 b1 = ((const int4*)dst)[(base >> 1) + 1];
                s0 = a0.x; s1 = a0.z; s2 = a1.x; s3 = a1.z;
                d0 = b0.x; d1 = b0.z; d2 = b1.x; d3 = b1.z;
            } else {
                int4 a = ((const int4*)src)[base >> 2];
                int4 c = ((const int4*)dst)[base >> 2];
                s0 = a.x; s1 = a.y; s2 = a.z; s3 = a.w;
                d0 = c.x; d1 = c.y; d2 = c.z; d3 = c.w;
            }
            g_esrc[atomicAdd(&g_cursor[d0], 1)] = s0;
            g_esrc[atomicAdd(&g_cursor[d1], 1)] = s1;
            g_esrc[atomicAdd(&g_cursor[d2], 1)] = s2;
            g_esrc[atomicAdd(&g_cursor[d3], 1)] = s3;
        } else {
            for (int e = base; e < E; e++) {
                int s = is64 ? (int)((const long long*)src)[e] : ((const int*)src)[e];
                int d = is64 ? (int)((const long long*)dst)[e] : ((const int*)dst)[e];
                g_esrc[atomicAdd(&g_cursor[d], 1)] = s;
            }
        }
    }
}

// ---------------- aggregation layer 1: 2 nodes per warp, 16 lanes each ----------------
// Each 16-lane group independently owns one node (full 256B feat16 row, uint4 per lane).
// No warp-collective ops in the body.
__global__ void k_agg1(int M) {
    int warp = (blockIdx.x * blockDim.x + threadIdx.x) >> 5;
    int lane = threadIdx.x & 31;
    int grp = lane >> 4;
    int seg = lane & 15;
    int node = warp * 2 + grp;
    if (node >= M) return;
    int beg = g_offs[node], end = g_offs[node + 1];
    const char* fb = (const char*)g_feat16;
    unsigned segoff = (unsigned)seg * 16u;
    float a0 = 0, a1 = 0, a2 = 0, a3 = 0, a4 = 0, a5 = 0, a6 = 0, a7 = 0;

    int e = beg;
    for (; e + 4 <= end; e += 4) {
        int i0 = __ldg(&g_esrc[e]);
        int i1 = __ldg(&g_esrc[e + 1]);
        int i2 = __ldg(&g_esrc[e + 2]);
        int i3 = __ldg(&g_esrc[e + 3]);
        uint4 t0 = *(const uint4*)(fb + (unsigned)i0 * 256u + segoff);
        uint4 t1 = *(const uint4*)(fb + (unsigned)i1 * 256u + segoff);
        uint4 t2 = *(const uint4*)(fb + (unsigned)i2 * 256u + segoff);
        uint4 t3 = *(const uint4*)(fb + (unsigned)i3 * 256u + segoff);
        __half2 sx = __hadd2(__hadd2(H2(t0.x), H2(t1.x)), __hadd2(H2(t2.x), H2(t3.x)));
        __half2 sy = __hadd2(__hadd2(H2(t0.y), H2(t1.y)), __hadd2(H2(t2.y), H2(t3.y)));
        __half2 sz = __hadd2(__hadd2(H2(t0.z), H2(t1.z)), __hadd2(H2(t2.z), H2(t3.z)));
        __half2 sw = __hadd2(__hadd2(H2(t0.w), H2(t1.w)), __hadd2(H2(t2.w), H2(t3.w)));
        float2 f;
        f = __half22float2(sx); a0 += f.x; a1 += f.y;
        f = __half22float2(sy); a2 += f.x; a3 += f.y;
        f = __half22float2(sz); a4 += f.x; a5 += f.y;
        f = __half22float2(sw); a6 += f.x; a7 += f.y;
    }
    for (; e < end; e++) {
        int i0 = __ldg(&g_esrc[e]);
        uint4 t0 = *(const uint4*)(fb + (unsigned)i0 * 256u + segoff);
        float2 f;
        f = __half22float2(H2(t0.x)); a0 += f.x; a1 += f.y;
        f = __half22float2(H2(t0.y)); a2 += f.x; a3 += f.y;
        f = __half22float2(H2(t0.z)); a4 += f.x; a5 += f.y;
        f = __half22float2(H2(t0.w)); a6 += f.x; a7 += f.y;
    }
    int deg = end - beg;
    float inv = 1.0f / (float)(deg > 0 ? deg : 1);
    __half2 h0 = __floats2half2_rn(a0 * inv, a1 * inv);
    __half2 h1 = __floats2half2_rn(a2 * inv, a3 * inv);
    __half2 h2 = __floats2half2_rn(a4 * inv, a5 * inv);
    __half2 h3 = __floats2half2_rn(a6 * inv, a7 * inv);
    *(uint4*)((char*)g_agg16 + (unsigned)node * 256u + segoff) =
        make_uint4(*(unsigned*)&h0, *(unsigned*)&h1, *(unsigned*)&h2, *(unsigned*)&h3);
}

// ---------------- fused fp16 tensor-core GEMM (layer1 + layer2) ----------------
#define LDA_H 40    // halves per smem row for load tiles
#define LDH1 136    // halves per smem row for h1 tile
#define SM_AS 0
#define SM_BS (2 * 128 * LDA_H)
#define SM_H1 (4 * 128 * LDA_H)
#define SMEM_FUSED_BYTES ((4 * 128 * LDA_H + 128 * LDH1) * 2)

__device__ __forceinline__ void ldsm4(unsigned& r0, unsigned& r1, unsigned& r2, unsigned& r3,
                                      unsigned addr) {
    asm volatile("ldmatrix.sync.aligned.m8n8.x4.shared.b16 {%0,%1,%2,%3}, [%4];"
                 : "=r"(r0), "=r"(r1), "=r"(r2), "=r"(r3) : "r"(addr));
}

__device__ __forceinline__ void mma_f16(float* c, const unsigned* a, const unsigned* b) {
    asm volatile("mma.sync.aligned.m16n8k16.row.col.f32.f16.f16.f32 "
                 "{%0,%1,%2,%3}, {%4,%5,%6,%7}, {%8,%9}, {%0,%1,%2,%3};"
                 : "+f"(c[0]), "+f"(c[1]), "+f"(c[2]), "+f"(c[3])
                 : "r"(a[0]), "r"(a[1]), "r"(a[2]), "r"(a[3]), "r"(b[0]), "r"(b[1]));
}

__device__ __forceinline__ void cp16(unsigned saddr, const void* gptr, int sz) {
    asm volatile("cp.async.cg.shared.global [%0], [%1], 16, %2;"
                 :: "r"(saddr), "l"(gptr), "r"(sz));
}
__device__ __forceinline__ void cp_commit() { asm volatile("cp.async.commit_group;"); }
__device__ __forceinline__ void cp_wait1() { asm volatile("cp.async.wait_group 1;"); }
__device__ __forceinline__ void cp_wait0() { asm volatile("cp.async.wait_group 0;"); }

__global__ __launch_bounds__(256) void k_gemm_fused(
    const float* __restrict__ b1, const float* __restrict__ b2,
    float* __restrict__ out, int M)
{
    extern __shared__ __half sh[];
    __half* H1 = sh + SM_H1;
    int tid = threadIdx.x, lane = tid & 31, wid = tid >> 5;
    int warp_m = wid >> 1, warp_n = wid & 1;
    int grp = lane >> 2, qk = lane & 3;
    int row0 = blockIdx.x * 128;
    unsigned sbase = (unsigned)__cvta_generic_to_shared(sh);
    unsigned h1base = (unsigned)__cvta_generic_to_shared(H1);
    int lrowA = (lane & 7) + ((lane >> 3) & 1) * 8;
    int lkA   = (lane >> 4) * 8;
    int lrowB = (lane & 7) + (lane >> 4) * 8;
    int lkB   = ((lane >> 3) & 1) * 8;
    int ldr = tid >> 2, ldc = tid & 3;
    int ldr2 = (tid + 256) >> 2;

    float acc[2][8][4];
    #pragma unroll
    for (int mt = 0; mt < 2; mt++)
        #pragma unroll
        for (int nt = 0; nt < 8; nt++)
            #pragma unroll
            for (int j = 0; j < 4; j++) acc[mt][nt][j] = 0.f;

    auto prefetch1 = [&](int kt, int buf) {
        const __half* Asrc = (kt < 4) ? g_feat16 : g_agg16;
        int kb = (kt & 3) * 32;
        {
            int grow = row0 + ldr;
            cp16(sbase + (SM_AS + buf * 128 * LDA_H + ldr * LDA_H + ldc * 8) * 2,
                 Asrc + (size_t)grow * 128 + kb + ldc * 8, (grow < M) ? 16 : 0);
            int grow2 = row0 + ldr2;
            cp16(sbase + (SM_AS + buf * 128 * LDA_H + ldr2 * LDA_H + ldc * 8) * 2,
                 Asrc + (size_t)grow2 * 128 + kb + ldc * 8, (grow2 < M) ? 16 : 0);
        }
        {
            cp16(sbase + (SM_BS + buf * 128 * LDA_H + ldr * LDA_H + ldc * 8) * 2,
                 g_w1t + ldr * 256 + kt * 32 + ldc * 8, 16);
            cp16(sbase + (SM_BS + buf * 128 * LDA_H + ldr2 * LDA_H + ldc * 8) * 2,
                 g_w1t + ldr2 * 256 + kt * 32 + ldc * 8, 16);
        }
    };
    auto prefetch2 = [&](int kt, int buf) {
        cp16(sbase + (SM_BS + buf * 128 * LDA_H + ldr * LDA_H + ldc * 8) * 2,
             g_w2t + ldr * 128 + kt * 32 + ldc * 8, 16);
        cp16(sbase + (SM_BS + buf * 128 * LDA_H + ldr2 * LDA_H + ldc * 8) * 2,
             g_w2t + ldr2 * 128 + kt * 32 + ldc * 8, 16);
    };
    auto compute = [&](int buf) {
        unsigned as0 = sbase + (SM_AS + buf * 128 * LDA_H) * 2;
        unsigned bs0 = sbase + (SM_BS + buf * 128 * LDA_H) * 2;
        #pragma unroll
        for (int ks = 0; ks < 2; ks++) {
            int k0 = ks * 16;
            unsigned a[2][4], bf[8][2];
            #pragma unroll
            for (int mt = 0; mt < 2; mt++) {
                int rb = warp_m * 32 + mt * 16;
                ldsm4(a[mt][0], a[mt][1], a[mt][2], a[mt][3],
                      as0 + ((rb + lrowA) * LDA_H + k0 + lkA) * 2);
            }
            #pragma unroll
            for (int g = 0; g < 4; g++) {
                int n0 = warp_n * 64 + g * 16;
                ldsm4(bf[2 * g][0], bf[2 * g][1], bf[2 * g + 1][0], bf[2 * g + 1][1],
                      bs0 + ((n0 + lrowB) * LDA_H + k0 + lkB) * 2);
            }
            #pragma unroll
            for (int mt = 0; mt < 2; mt++)
                #pragma unroll
                for (int nt = 0; nt < 8; nt++)
                    mma_f16(acc[mt][nt], a[mt], bf[nt]);
        }
    };

    // ================= layer 1 =================
    prefetch1(0, 0); cp_commit();
    for (int kt = 0; kt < 8; kt++) {
        int cur = kt & 1;
        if (kt < 7) { prefetch1(kt + 1, cur ^ 1); cp_commit(); cp_wait1(); }
        else cp_wait0();
        __syncthreads();
        compute(cur);
        __syncthreads();
    }
    #pragma unroll
    for (int mt = 0; mt < 2; mt++) {
        #pragma unroll
        for (int nt = 0; nt < 8; nt++) {
            int c = warp_n * 64 + nt * 8 + 2 * qk;
            float bx = b1[c], by = b1[c + 1];
            int r = warp_m * 32 + mt * 16 + grp;
            __half2 h = __floats2half2_rn(fmaxf(acc[mt][nt][0] + bx, 0.f),
                                          fmaxf(acc[mt][nt][1] + by, 0.f));
            *(__half2*)&H1[r * LDH1 + c] = h;
            __half2 h2 = __floats2half2_rn(fmaxf(acc[mt][nt][2] + bx, 0.f),
                                           fmaxf(acc[mt][nt][3] + by, 0.f));
            *(__half2*)&H1[(r + 8) * LDH1 + c] = h2;
            #pragma unroll
            for (int j = 0; j < 4; j++) acc[mt][nt][j] = 0.f;
        }
    }
    __syncthreads();

    // ================= layer 2 =================
    prefetch2(0, 0); cp_commit();
    for (int kt = 0; kt < 4; kt++) {
        int cur = kt & 1;
        if (kt < 3) { prefetch2(kt + 1, cur ^ 1); cp_commit(); cp_wait1(); }
        else cp_wait0();
        __syncthreads();
        int kb = kt * 32;
        unsigned bs0 = sbase + (SM_BS + cur * 128 * LDA_H) * 2;
        #pragma unroll
        for (int ks = 0; ks < 2; ks++) {
            int k0 = kb + ks * 16;
            unsigned a[2][4], bf[8][2];
            #pragma unroll
            for (int mt = 0; mt < 2; mt++) {
                int rb = warp_m * 32 + mt * 16;
                ldsm4(a[mt][0], a[mt][1], a[mt][2], a[mt][3],
                      h1base + ((rb + lrowA) * LDH1 + k0 + lkA) * 2);
            }
            #pragma unroll
            for (int g = 0; g < 4; g++) {
                int n0 = warp_n * 64 + g * 16;
                ldsm4(bf[2 * g][0], bf[2 * g][1], bf[2 * g + 1][0], bf[2 * g + 1][1],
                      bs0 + ((n0 + lrowB) * LDA_H + ks * 16 + lkB) * 2);
            }
            #pragma unroll
            for (int mt = 0; mt < 2; mt++)
                #pragma unroll
                for (int nt = 0; nt < 8; nt++)
                    mma_f16(acc[mt][nt], a[mt], bf[nt]);
        }
        __syncthreads();
    }
    #pragma unroll
    for (int mt = 0; mt < 2; mt++) {
        #pragma unroll
        for (int nt = 0; nt < 8; nt++) {
            int c = warp_n * 64 + nt * 8 + 2 * qk;
            bool self_half = (c < 64);
            float bx = 0.f, by = 0.f;
            if (self_half) { bx = b2[c]; by = b2[c + 1]; }
            int r = row0 + warp_m * 32 + mt * 16 + grp;
            #pragma unroll
            for (int h = 0; h < 2; h++) {
                int rr = r + h * 8;
                if (rr < M) {
                    float ox = acc[mt][nt][2 * h + 0] + bx;
                    float oy = acc[mt][nt][2 * h + 1] + by;
                    if (self_half) {
                        *(float2*)&out[(size_t)rr * 64 + c] = make_float2(ox, oy);
                    } else {
                        __half2 hv = __floats2half2_rn(ox, oy);
                        *(__half2*)&g_p2h[(size_t)rr * 64 + (c - 64)] = hv;
                    }
                }
            }
        }
    }
}

// ---------------- aggregation layer 2: 4 nodes per warp, 8 lanes each ----------------
// Each 8-lane group independently owns one node (full 128B p2h row, uint4 per lane).
__global__ void k_agg2(float* __restrict__ out, int M) {
    int warp = (blockIdx.x * blockDim.x + threadIdx.x) >> 5;
    int lane = threadIdx.x & 31;
    int grp = lane >> 3;        // 0..3
    int seg = lane & 7;         // 0..7
    int node = warp * 4 + grp;
    if (node >= M) return;
    int beg = g_offs[node], end = g_offs[node + 1];
    const char* pb = (const char*)g_p2h;
    unsigned segoff = (unsigned)seg * 16u;
    float a0 = 0, a1 = 0, a2 = 0, a3 = 0, a4 = 0, a5 = 0, a6 = 0, a7 = 0;

    int e = beg;
    for (; e + 4 <= end; e += 4) {
        int i0 = __ldg(&g_esrc[e]);
        int i1 = __ldg(&g_esrc[e + 1]);
        int i2 = __ldg(&g_esrc[e + 2]);
        int i3 = __ldg(&g_esrc[e + 3]);
        uint4 t0 = *(const uint4*)(pb + (unsigned)i0 * 128u + segoff);
        uint4 t1 = *(const uint4*)(pb + (unsigned)i1 * 128u + segoff);
        uint4 t2 = *(const uint4*)(pb + (unsigned)i2 * 128u + segoff);
        uint4 t3 = *(const uint4*)(pb + (unsigned)i3 * 128u + segoff);
        __half2 sx = __hadd2(__hadd2(H2(t0.x), H2(t1.x)), __hadd2(H2(t2.x), H2(t3.x)));
        __half2 sy = __hadd2(__hadd2(H2(t0.y), H2(t1.y)), __hadd2(H2(t2.y), H2(t3.y)));
        __half2 sz = __hadd2(__hadd2(H2(t0.z), H2(t1.z)), __hadd2(H2(t2.z), H2(t3.z)));
        __half2 sw = __hadd2(__hadd2(H2(t0.w), H2(t1.w)), __hadd2(H2(t2.w), H2(t3.w)));
        float2 f;
        f = __half22float2(sx); a0 += f.x; a1 += f.y;
        f = __half22float2(sy); a2 += f.x; a3 += f.y;
        f = __half22float2(sz); a4 += f.x; a5 += f.y;
        f = __half22float2(sw); a6 += f.x; a7 += f.y;
    }
    for (; e < end; e++) {
        int i0 = __ldg(&g_esrc[e]);
        uint4 t0 = *(const uint4*)(pb + (unsigned)i0 * 128u + segoff);
        float2 f;
        f = __half22float2(H2(t0.x)); a0 += f.x; a1 += f.y;
        f = __half22float2(H2(t0.y)); a2 += f.x; a3 += f.y;
        f = __half22float2(H2(t0.z)); a4 += f.x; a5 += f.y;
        f = __half22float2(H2(t0.w)); a6 += f.x; a7 += f.y;
    }
    int deg = end - beg;
    float inv = 1.0f / (float)(deg > 0 ? deg : 1);
    float* op = out + (size_t)node * 64 + seg * 8;
    float4 o0 = *(float4*)op;
    float4 o1 = *(float4*)(op + 4);
    o0.x += a0 * inv; o0.y += a1 * inv; o0.z += a2 * inv; o0.w += a3 * inv;
    o1.x += a4 * inv; o1.y += a5 * inv; o1.z += a6 * inv; o1.w += a7 * inv;
    *(float4*)op = o0;
    *(float4*)(op + 4) = o1;
}

// ---------------- launch ----------------
extern "C" void kernel_launch(void* const* d_in, const int* in_sizes, int n_in,
                              void* d_out, int out_size) {
    const float* feat = (const float*)d_in[0];
    const void*  src  = d_in[1];
    const void*  dst  = d_in[2];
    const float* Ws1  = (const float*)d_in[3];
    const float* Wn1  = (const float*)d_in[4];
    const float* b1   = (const float*)d_in[5];
    const float* Ws2  = (const float*)d_in[6];
    const float* Wn2  = (const float*)d_in[7];
    const float* b2   = (const float*)d_in[8];

    int M = in_sizes[0] / 128;   // 50000
    int E = in_sizes[1];         // 800000

    static int s_attr_done = 0;
    if (!s_attr_done) {
        cudaFuncSetAttribute(k_gemm_fused, cudaFuncAttributeMaxDynamicSharedMemorySize,
                             SMEM_FUSED_BYTES);
        s_attr_done = 1;
    }

    k_prep<<<PREP_BLOCKS, PREP_TPB>>>((const float4*)feat, src, dst, Ws1, Wn1, Ws2, Wn2, M, E);

    int agg1_blocks = (M + 15) / 16;        // 2 nodes per warp, 8 warps per block
    k_agg1<<<agg1_blocks, 256>>>(M);

    int gemm_blocks = (M + 127) / 128;
    k_gemm_fused<<<gemm_blocks, 256, SMEM_FUSED_BYTES>>>(b1, b2, (float*)d_out, M);

    int agg2_blocks = (M + 31) / 32;        // 4 nodes per warp, 8 warps per block
    k_agg2<<<agg2_blocks, 256>>>((float*)d_out, M);
}

// round 17
// speedup vs baseline: 1.0076x; 1.0076x over previous
#include <cuda_runtime.h>
#include <cuda_fp16.h>

#define N_NODES 50000
#define N_EDGES 800000
#define PREP_BLOCKS 444     // 148 SMs x 3 blocks, provably co-resident with __launch_bounds__(512,3)
#define PREP_TPB 512

#define H2(u) (*(__half2*)&(u))

// ---------------- device scratch (static: no allocation allowed) ----------------
// NOTE: g_deg is zero-initialized at module load and re-zeroed at the end of each
// launch (Phase D), so every launch sees deg == 0 without a dedicated zeroing phase.
__device__ __align__(16) int g_deg[N_NODES];
__device__ __align__(16) int g_offs[N_NODES + 4];
__device__ __align__(16) int g_cursor[N_NODES];
__device__ __align__(16) int g_esrc[N_EDGES];
__device__ int g_bsum[128];
__device__ __align__(16) __half g_feat16[(size_t)N_NODES * 128];
__device__ __align__(16) __half g_agg16[(size_t)N_NODES * 128];
__device__ __align__(16) __half g_p2h[(size_t)N_NODES * 64];
__device__ __align__(16) __half g_w1t[128 * 256];   // [n][k] fp16
__device__ __align__(16) __half g_w2t[128 * 128];   // [n][k] fp16

// ---------------- grid barrier (444 x 512-thread blocks: 3/SM, all co-resident) ----------------
__device__ unsigned g_bar_count = 0;
__device__ volatile unsigned g_bar_gen = 0;

__device__ __forceinline__ void grid_barrier() {
    __syncthreads();
    if (threadIdx.x == 0) {
        unsigned gen = g_bar_gen;
        __threadfence();
        if (atomicAdd(&g_bar_count, 1u) == gridDim.x - 1) {
            g_bar_count = 0;
            __threadfence();
            g_bar_gen = gen + 1;
        } else {
            while (g_bar_gen == gen) { }
        }
        __threadfence();
    }
    __syncthreads();
}

__device__ __forceinline__ int wscan_incl(int x, int lane) {
    #pragma unroll
    for (int o = 1; o < 32; o <<= 1) {
        int y = __shfl_up_sync(0xFFFFFFFFu, x, o);
        if (lane >= o) x += y;
    }
    return x;
}

// ---------------- mega prep kernel (CSC build + feat/weight prep + agg1) ----------------
__global__ __launch_bounds__(PREP_TPB, 3) void k_prep(
    const float4* __restrict__ feat, const void* __restrict__ src, const void* __restrict__ dst,
    const float* __restrict__ Ws1, const float* __restrict__ Wn1,
    const float* __restrict__ Ws2, const float* __restrict__ Wn2,
    int M, int E)
{
    int tid = threadIdx.x, b = blockIdx.x;
    int lane = tid & 31, wid = tid >> 5;    // wid 0..15
    int gt = b * PREP_TPB + tid;
    int GT = gridDim.x * PREP_TPB;
    __shared__ int s_any;
    __shared__ int wsum[16];

    // ---- block-local dtype detection (no global communication, no barrier) ----
    if (tid == 0) s_any = 0;
    __syncthreads();
    if (((const unsigned*)src)[2 * tid + 1]) s_any = 1;  // benign race
    __syncthreads();
    int is64 = (s_any == 0) ? 1 : 0;

    // ---- Phase B: histogram (deg pre-zeroed) + feat->fp16 + weight prep ----
    for (int base = gt * 4; base < E; base += GT * 4) {
        if (base + 3 < E) {
            int d0, d1, d2, d3;
            if (is64) {
                int4 w0 = ((const int4*)dst)[base >> 1];
                int4 w1 = ((const int4*)dst)[(base >> 1) + 1];
                d0 = w0.x; d1 = w0.z; d2 = w1.x; d3 = w1.z;
            } else {
                int4 w = ((const int4*)dst)[base >> 2];
                d0 = w.x; d1 = w.y; d2 = w.z; d3 = w.w;
            }
            atomicAdd(&g_deg[d0], 1); atomicAdd(&g_deg[d1], 1);
            atomicAdd(&g_deg[d2], 1); atomicAdd(&g_deg[d3], 1);
        } else {
            for (int e = base; e < E; e++) {
                int d = is64 ? (int)((const long long*)dst)[e] : ((const int*)dst)[e];
                atomicAdd(&g_deg[d], 1);
            }
        }
    }
    int TU = (M * 128) / 8;
    for (int i = gt; i < TU; i += GT) {
        float4 a = feat[2 * i], c = feat[2 * i + 1];
        __half2 h0 = __floats2half2_rn(a.x, a.y);
        __half2 h1 = __floats2half2_rn(a.z, a.w);
        __half2 h2 = __floats2half2_rn(c.x, c.y);
        __half2 h3 = __floats2half2_rn(c.z, c.w);
        ((uint4*)g_feat16)[i] = make_uint4(*(unsigned*)&h0, *(unsigned*)&h1,
                                           *(unsigned*)&h2, *(unsigned*)&h3);
    }
    for (int i = gt; i < 128 * 256; i += GT) {
        int k = i >> 7, n = i & 127;
        float v = (k < 128) ? Ws1[k * 128 + n] : Wn1[(k - 128) * 128 + n];
        g_w1t[n * 256 + k] = __float2half_rn(v);
    }
    for (int i = gt; i < 128 * 128; i += GT) {
        int k = i >> 7, n = i & 127;
        float v = (n < 64) ? Ws2[k * 64 + n] : Wn2[k * 64 + (n - 64)];
        g_w2t[n * 128 + k] = __float2half_rn(v);
    }
    grid_barrier();

    // ---- Phase C1: per-block local scan (512 elems per block) ----
    int nsb = (M + PREP_TPB - 1) / PREP_TPB;     // 98
    int v = 0, excl = 0;
    if (b < nsb) {
        int i = b * PREP_TPB + tid;
        v = (i < M) ? g_deg[i] : 0;
        int x = wscan_incl(v, lane);
        if (lane == 31) wsum[wid] = x;
        __syncthreads();
        if (wid == 0) {
            int w = (lane < 16) ? wsum[lane] : 0;
            w = wscan_incl(w, lane);
            if (lane < 16) wsum[lane] = w;
        }
        __syncthreads();
        int wex = wid ? wsum[wid - 1] : 0;
        excl = wex + x - v;
        if (tid == 0) g_bsum[b] = wsum[15];
    }
    grid_barrier();

    // ---- Phase C2: apply (each block redundantly computes its own carry) ----
    if (b < nsb) {
        int carry = 0;
        for (int idx = lane; idx < b; idx += 32) carry += g_bsum[idx];
        #pragma unroll
        for (int o = 16; o > 0; o >>= 1) carry += __shfl_xor_sync(0xFFFFFFFFu, carry, o);
        int i = b * PREP_TPB + tid;
        int e2 = carry + excl;
        if (i < M) {
            g_offs[i] = e2;
            g_cursor[i] = e2;
            if (i == M - 1) g_offs[M] = e2 + v;
        }
    }
    grid_barrier();

    // ---- Phase D: scatter edges into CSC + re-zero deg for next launch ----
    for (int base = gt * 4; base < E; base += GT * 4) {
        if (base + 3 < E) {
            int s0, s1, s2, s3, d0, d1, d2, d3;
            if (is64) {
                int4 a0 = ((const int4*)src)[base >> 1];
                int4 a1 = ((const int4*)src)[(base >> 1) + 1];
                int4 b0 = ((const int4*)dst)[base >> 1];
                int4 b1 = ((const int4*)dst)[(base >> 1) + 1];
                s0 = a0.x; s1 = a0.z; s2 = a1.x; s3 = a1.z;
                d0 = b0.x; d1 = b0.z; d2 = b1.x; d3 = b1.z;
            } else {
                int4 a = ((const int4*)src)[base >> 2];
                int4 c = ((const int4*)dst)[base >> 2];
                s0 = a.x; s1 = a.y; s2 = a.z; s3 = a.w;
                d0 = c.x; d1 = c.y; d2 = c.z; d3 = c.w;
            }
            g_esrc[atomicAdd(&g_cursor[d0], 1)] = s0;
            g_esrc[atomicAdd(&g_cursor[d1], 1)] = s1;
            g_esrc[atomicAdd(&g_cursor[d2], 1)] = s2;
            g_esrc[atomicAdd(&g_cursor[d3], 1)] = s3;
        } else {
            for (int e = base; e < E; e++) {
                int s = is64 ? (int)((const long long*)src)[e] : ((const int*)src)[e];
                int d = is64 ? (int)((const long long*)dst)[e] : ((const int*)dst)[e];
                g_esrc[atomicAdd(&g_cursor[d], 1)] = s;
            }
        }
    }
    for (int i = gt; i < M; i += GT) g_deg[i] = 0;   // deg not read in this phase
    grid_barrier();

    // ---- Phase E: aggregation layer 1 (2 nodes per warp, HADD2 tree) ----
    {
        int grp = lane >> 4;
        int seg = lane & 15;
        const char* fb = (const char*)g_feat16;
        unsigned segoff = (unsigned)seg * 16u;
        int nwarp = gridDim.x * 16;
        for (int pair = b * 16 + wid; pair * 2 < M; pair += nwarp) {
            int node = pair * 2 + grp;
            if (node >= M) continue;
            int beg = g_offs[node], end = g_offs[node + 1];
            float a0 = 0, a1 = 0, a2 = 0, a3 = 0, a4 = 0, a5 = 0, a6 = 0, a7 = 0;
            int e = beg;
            for (; e + 4 <= end; e += 4) {
                int i0 = __ldg(&g_esrc[e]);
                int i1 = __ldg(&g_esrc[e + 1]);
                int i2 = __ldg(&g_esrc[e + 2]);
                int i3 = __ldg(&g_esrc[e + 3]);
                uint4 t0 = *(const uint4*)(fb + (unsigned)i0 * 256u + segoff);
                uint4 t1 = *(const uint4*)(fb + (unsigned)i1 * 256u + segoff);
                uint4 t2 = *(const uint4*)(fb + (unsigned)i2 * 256u + segoff);
                uint4 t3 = *(const uint4*)(fb + (unsigned)i3 * 256u + segoff);
                __half2 sx = __hadd2(__hadd2(H2(t0.x), H2(t1.x)), __hadd2(H2(t2.x), H2(t3.x)));
                __half2 sy = __hadd2(__hadd2(H2(t0.y), H2(t1.y)), __hadd2(H2(t2.y), H2(t3.y)));
                __half2 sz = __hadd2(__hadd2(H2(t0.z), H2(t1.z)), __hadd2(H2(t2.z), H2(t3.z)));
                __half2 sw = __hadd2(__hadd2(H2(t0.w), H2(t1.w)), __hadd2(H2(t2.w), H2(t3.w)));
                float2 f;
                f = __half22float2(sx); a0 += f.x; a1 += f.y;
                f = __half22float2(sy); a2 += f.x; a3 += f.y;
                f = __half22float2(sz); a4 += f.x; a5 += f.y;
                f = __half22float2(sw); a6 += f.x; a7 += f.y;
            }
            for (; e < end; e++) {
                int i0 = __ldg(&g_esrc[e]);
                uint4 t0 = *(const uint4*)(fb + (unsigned)i0 * 256u + segoff);
                float2 f;
                f = __half22float2(H2(t0.x)); a0 += f.x; a1 += f.y;
                f = __half22float2(H2(t0.y)); a2 += f.x; a3 += f.y;
                f = __half22float2(H2(t0.z)); a4 += f.x; a5 += f.y;
                f = __half22float2(H2(t0.w)); a6 += f.x; a7 += f.y;
            }
            int deg = end - beg;
            float inv = 1.0f / (float)(deg > 0 ? deg : 1);
            __half2 h0 = __floats2half2_rn(a0 * inv, a1 * inv);
            __half2 h1 = __floats2half2_rn(a2 * inv, a3 * inv);
            __half2 h2 = __floats2half2_rn(a4 * inv, a5 * inv);
            __half2 h3 = __floats2half2_rn(a6 * inv, a7 * inv);
            *(uint4*)((char*)g_agg16 + (unsigned)node * 256u + segoff) =
                make_uint4(*(unsigned*)&h0, *(unsigned*)&h1, *(unsigned*)&h2, *(unsigned*)&h3);
        }
    }
}

// ---------------- fused fp16 tensor-core GEMM (layer1 + layer2) ----------------
#define LDA_H 40    // halves per smem row for load tiles
#define LDH1 136    // halves per smem row for h1 tile
#define SM_AS 0
#define SM_BS (2 * 128 * LDA_H)
#define SM_H1 (4 * 128 * LDA_H)
#define SMEM_FUSED_BYTES ((4 * 128 * LDA_H + 128 * LDH1) * 2)

__device__ __forceinline__ void ldsm4(unsigned& r0, unsigned& r1, unsigned& r2, unsigned& r3,
                                      unsigned addr) {
    asm volatile("ldmatrix.sync.aligned.m8n8.x4.shared.b16 {%0,%1,%2,%3}, [%4];"
                 : "=r"(r0), "=r"(r1), "=r"(r2), "=r"(r3) : "r"(addr));
}

__device__ __forceinline__ void mma_f16(float* c, const unsigned* a, const unsigned* b) {
    asm volatile("mma.sync.aligned.m16n8k16.row.col.f32.f16.f16.f32 "
                 "{%0,%1,%2,%3}, {%4,%5,%6,%7}, {%8,%9}, {%0,%1,%2,%3};"
                 : "+f"(c[0]), "+f"(c[1]), "+f"(c[2]), "+f"(c[3])
                 : "r"(a[0]), "r"(a[1]), "r"(a[2]), "r"(a[3]), "r"(b[0]), "r"(b[1]));
}

__device__ __forceinline__ void cp16(unsigned saddr, const void* gptr, int sz) {
    asm volatile("cp.async.cg.shared.global [%0], [%1], 16, %2;"
                 :: "r"(saddr), "l"(gptr), "r"(sz));
}
__device__ __forceinline__ void cp_commit() { asm volatile("cp.async.commit_group;"); }
__device__ __forceinline__ void cp_wait1() { asm volatile("cp.async.wait_group 1;"); }
__device__ __forceinline__ void cp_wait0() { asm volatile("cp.async.wait_group 0;"); }

__global__ __launch_bounds__(256) void k_gemm_fused(
    const float* __restrict__ b1, const float* __restrict__ b2,
    float* __restrict__ out, int M)
{
    extern __shared__ __half sh[];
    __half* H1 = sh + SM_H1;
    int tid = threadIdx.x, lane = tid & 31, wid = tid >> 5;
    int warp_m = wid >> 1, warp_n = wid & 1;
    int grp = lane >> 2, qk = lane & 3;
    int row0 = blockIdx.x * 128;
    unsigned sbase = (unsigned)__cvta_generic_to_shared(sh);
    unsigned h1base = (unsigned)__cvta_generic_to_shared(H1);
    int lrowA = (lane & 7) + ((lane >> 3) & 1) * 8;
    int lkA   = (lane >> 4) * 8;
    int lrowB = (lane & 7) + (lane >> 4) * 8;
    int lkB   = ((lane >> 3) & 1) * 8;
    int ldr = tid >> 2, ldc = tid & 3;
    int ldr2 = (tid + 256) >> 2;

    float acc[2][8][4];
    #pragma unroll
    for (int mt = 0; mt < 2; mt++)
        #pragma unroll
        for (int nt = 0; nt < 8; nt++)
            #pragma unroll
            for (int j = 0; j < 4; j++) acc[mt][nt][j] = 0.f;

    auto prefetch1 = [&](int kt, int buf) {
        const __half* Asrc = (kt < 4) ? g_feat16 : g_agg16;
        int kb = (kt & 3) * 32;
        {
            int grow = row0 + ldr;
            cp16(sbase + (SM_AS + buf * 128 * LDA_H + ldr * LDA_H + ldc * 8) * 2,
                 Asrc + (size_t)grow * 128 + kb + ldc * 8, (grow < M) ? 16 : 0);
            int grow2 = row0 + ldr2;
            cp16(sbase + (SM_AS + buf * 128 * LDA_H + ldr2 * LDA_H + ldc * 8) * 2,
                 Asrc + (size_t)grow2 * 128 + kb + ldc * 8, (grow2 < M) ? 16 : 0);
        }
        {
            cp16(sbase + (SM_BS + buf * 128 * LDA_H + ldr * LDA_H + ldc * 8) * 2,
                 g_w1t + ldr * 256 + kt * 32 + ldc * 8, 16);
            cp16(sbase + (SM_BS + buf * 128 * LDA_H + ldr2 * LDA_H + ldc * 8) * 2,
                 g_w1t + ldr2 * 256 + kt * 32 + ldc * 8, 16);
        }
    };
    auto prefetch2 = [&](int kt, int buf) {
        cp16(sbase + (SM_BS + buf * 128 * LDA_H + ldr * LDA_H + ldc * 8) * 2,
             g_w2t + ldr * 128 + kt * 32 + ldc * 8, 16);
        cp16(sbase + (SM_BS + buf * 128 * LDA_H + ldr2 * LDA_H + ldc * 8) * 2,
             g_w2t + ldr2 * 128 + kt * 32 + ldc * 8, 16);
    };
    auto compute = [&](int buf) {
        unsigned as0 = sbase + (SM_AS + buf * 128 * LDA_H) * 2;
        unsigned bs0 = sbase + (SM_BS + buf * 128 * LDA_H) * 2;
        #pragma unroll
        for (int ks = 0; ks < 2; ks++) {
            int k0 = ks * 16;
            unsigned a[2][4], bf[8][2];
            #pragma unroll
            for (int mt = 0; mt < 2; mt++) {
                int rb = warp_m * 32 + mt * 16;
                ldsm4(a[mt][0], a[mt][1], a[mt][2], a[mt][3],
                      as0 + ((rb + lrowA) * LDA_H + k0 + lkA) * 2);
            }
            #pragma unroll
            for (int g = 0; g < 4; g++) {
                int n0 = warp_n * 64 + g * 16;
                ldsm4(bf[2 * g][0], bf[2 * g][1], bf[2 * g + 1][0], bf[2 * g + 1][1],
                      bs0 + ((n0 + lrowB) * LDA_H + k0 + lkB) * 2);
            }
            #pragma unroll
            for (int mt = 0; mt < 2; mt++)
                #pragma unroll
                for (int nt = 0; nt < 8; nt++)
                    mma_f16(acc[mt][nt], a[mt], bf[nt]);
        }
    };

    // ================= layer 1 =================
    prefetch1(0, 0); cp_commit();
    for (int kt = 0; kt < 8; kt++) {
        int cur = kt & 1;
        if (kt < 7) { prefetch1(kt + 1, cur ^ 1); cp_commit(); cp_wait1(); }
        else cp_wait0();
        __syncthreads();
        compute(cur);
        __syncthreads();
    }
    #pragma unroll
    for (int mt = 0; mt < 2; mt++) {
        #pragma unroll
        for (int nt = 0; nt < 8; nt++) {
            int c = warp_n * 64 + nt * 8 + 2 * qk;
            float bx = b1[c], by = b1[c + 1];
            int r = warp_m * 32 + mt * 16 + grp;
            __half2 h = __floats2half2_rn(fmaxf(acc[mt][nt][0] + bx, 0.f),
                                          fmaxf(acc[mt][nt][1] + by, 0.f));
            *(__half2*)&H1[r * LDH1 + c] = h;
            __half2 h2 = __floats2half2_rn(fmaxf(acc[mt][nt][2] + bx, 0.f),
                                           fmaxf(acc[mt][nt][3] + by, 0.f));
            *(__half2*)&H1[(r + 8) * LDH1 + c] = h2;
            #pragma unroll
            for (int j = 0; j < 4; j++) acc[mt][nt][j] = 0.f;
        }
    }
    __syncthreads();

    // ================= layer 2 =================
    prefetch2(0, 0); cp_commit();
    for (int kt = 0; kt < 4; kt++) {
        int cur = kt & 1;
        if (kt < 3) { prefetch2(kt + 1, cur ^ 1); cp_commit(); cp_wait1(); }
        else cp_wait0();
        __syncthreads();
        int kb = kt * 32;
        unsigned bs0 = sbase + (SM_BS + cur * 128 * LDA_H) * 2;
        #pragma unroll
        for (int ks = 0; ks < 2; ks++) {
            int k0 = kb + ks * 16;
            unsigned a[2][4], bf[8][2];
            #pragma unroll
            for (int mt = 0; mt < 2; mt++) {
                int rb = warp_m * 32 + mt * 16;
                ldsm4(a[mt][0], a[mt][1], a[mt][2], a[mt][3],
                      h1base + ((rb + lrowA) * LDH1 + k0 + lkA) * 2);
            }
            #pragma unroll
            for (int g = 0; g < 4; g++) {
                int n0 = warp_n * 64 + g * 16;
                ldsm4(bf[2 * g][0], bf[2 * g][1], bf[2 * g + 1][0], bf[2 * g + 1][1],
                      bs0 + ((n0 + lrowB) * LDA_H + ks * 16 + lkB) * 2);
            }
            #pragma unroll
            for (int mt = 0; mt < 2; mt++)
                #pragma unroll
                for (int nt = 0; nt < 8; nt++)
                    mma_f16(acc[mt][nt], a[mt], bf[nt]);
        }
        __syncthreads();
    }
    #pragma unroll
    for (int mt = 0; mt < 2; mt++) {
        #pragma unroll
        for (int nt = 0; nt < 8; nt++) {
            int c = warp_n * 64 + nt * 8 + 2 * qk;
            bool self_half = (c < 64);
            float bx = 0.f, by = 0.f;
            if (self_half) { bx = b2[c]; by = b2[c + 1]; }
            int r = row0 + warp_m * 32 + mt * 16 + grp;
            #pragma unroll
            for (int h = 0; h < 2; h++) {
                int rr = r + h * 8;
                if (rr < M) {
                    float ox = acc[mt][nt][2 * h + 0] + bx;
                    float oy = acc[mt][nt][2 * h + 1] + by;
                    if (self_half) {
                        *(float2*)&out[(size_t)rr * 64 + c] = make_float2(ox, oy);
                    } else {
                        __half2 hv = __floats2half2_rn(ox, oy);
                        *(__half2*)&g_p2h[(size_t)rr * 64 + (c - 64)] = hv;
                    }
                }
            }
        }
    }
}

// ---------------- aggregation layer 2: 4 nodes per warp, 8 lanes each ----------------
__global__ void k_agg2(float* __restrict__ out, int M) {
    int warp = (blockIdx.x * blockDim.x + threadIdx.x) >> 5;
    int lane = threadIdx.x & 31;
    int grp = lane >> 3;        // 0..3
    int seg = lane & 7;         // 0..7
    int node = warp * 4 + grp;
    if (node >= M) return;
    int beg = g_offs[node], end = g_offs[node + 1];
    const char* pb = (const char*)g_p2h;
    unsigned segoff = (unsigned)seg * 16u;
    float a0 = 0, a1 = 0, a2 = 0, a3 = 0, a4 = 0, a5 = 0, a6 = 0, a7 = 0;

    int e = beg;
    for (; e + 4 <= end; e += 4) {
        int i0 = __ldg(&g_esrc[e]);
        int i1 = __ldg(&g_esrc[e + 1]);
        int i2 = __ldg(&g_esrc[e + 2]);
        int i3 = __ldg(&g_esrc[e + 3]);
        uint4 t0 = *(const uint4*)(pb + (unsigned)i0 * 128u + segoff);
        uint4 t1 = *(const uint4*)(pb + (unsigned)i1 * 128u + segoff);
        uint4 t2 = *(const uint4*)(pb + (unsigned)i2 * 128u + segoff);
        uint4 t3 = *(const uint4*)(pb + (unsigned)i3 * 128u + segoff);
        __half2 sx = __hadd2(__hadd2(H2(t0.x), H2(t1.x)), __hadd2(H2(t2.x), H2(t3.x)));
        __half2 sy = __hadd2(__hadd2(H2(t0.y), H2(t1.y)), __hadd2(H2(t2.y), H2(t3.y)));
        __half2 sz = __hadd2(__hadd2(H2(t0.z), H2(t1.z)), __hadd2(H2(t2.z), H2(t3.z)));
        __half2 sw = __hadd2(__hadd2(H2(t0.w), H2(t1.w)), __hadd2(H2(t2.w), H2(t3.w)));
        float2 f;
        f = __half22float2(sx); a0 += f.x; a1 += f.y;
        f = __half22float2(sy); a2 += f.x; a3 += f.y;
        f = __half22float2(sz); a4 += f.x; a5 += f.y;
        f = __half22float2(sw); a6 += f.x; a7 += f.y;
    }
    for (; e < end; e++) {
        int i0 = __ldg(&g_esrc[e]);
        uint4 t0 = *(const uint4*)(pb + (unsigned)i0 * 128u + segoff);
        float2 f;
        f = __half22float2(H2(t0.x)); a0 += f.x; a1 += f.y;
        f = __half22float2(H2(t0.y)); a2 += f.x; a3 += f.y;
        f = __half22float2(H2(t0.z)); a4 += f.x; a5 += f.y;
        f = __half22float2(H2(t0.w)); a6 += f.x; a7 += f.y;
    }
    int deg = end - beg;
    float inv = 1.0f / (float)(deg > 0 ? deg : 1);
    float* op = out + (size_t)node * 64 + seg * 8;
    float4 o0 = *(float4*)op;
    float4 o1 = *(float4*)(op + 4);
    o0.x += a0 * inv; o0.y += a1 * inv; o0.z += a2 * inv; o0.w += a3 * inv;
    o1.x += a4 * inv; o1.y += a5 * inv; o1.z += a6 * inv; o1.w += a7 * inv;
    *(float4*)op = o0;
    *(float4*)(op + 4) = o1;
}

// ---------------- launch ----------------
extern "C" void kernel_launch(void* const* d_in, const int* in_sizes, int n_in,
                              void* d_out, int out_size) {
    const float* feat = (const float*)d_in[0];
    const void*  src  = d_in[1];
    const void*  dst  = d_in[2];
    const float* Ws1  = (const float*)d_in[3];
    const float* Wn1  = (const float*)d_in[4];
    const float* b1   = (const float*)d_in[5];
    const float* Ws2  = (const float*)d_in[6];
    const float* Wn2  = (const float*)d_in[7];
    const float* b2   = (const float*)d_in[8];

    int M = in_sizes[0] / 128;   // 50000
    int E = in_sizes[1];         // 800000

    static int s_attr_done = 0;
    if (!s_attr_done) {
        cudaFuncSetAttribute(k_gemm_fused, cudaFuncAttributeMaxDynamicSharedMemorySize,
                             SMEM_FUSED_BYTES);
        s_attr_done = 1;
    }

    k_prep<<<PREP_BLOCKS, PREP_TPB>>>((const float4*)feat, src, dst, Ws1, Wn1, Ws2, Wn2, M, E);

    int gemm_blocks = (M + 127) / 128;
    k_gemm_fused<<<gemm_blocks, 256, SMEM_FUSED_BYTES>>>(b1, b2, (float*)d_out, M);

    int agg2_blocks = (M + 31) / 32;        // 4 nodes per warp, 8 warps per block
    k_agg2<<<agg2_blocks, 256>>>((float*)d_out, M);
}